// round 1
// baseline (speedup 1.0000x reference)
#include <cuda_runtime.h>
#include <math_constants.h>

// Problem constants (from reference setup_inputs)
constexpr int B  = 4;
constexpr int H  = 64;
constexpr int W  = 64;
constexpr int C  = 256;
constexpr int NR = 256;   // rois per image
constexpr int PH = 7;
constexpr int PW = 7;

constexpr int C4    = C / 4;       // float4 groups per position = 64
constexpr int NGRP  = 8;           // bin-parallel groups per block
constexpr int NTHR  = NGRP * C4;   // 512 threads

// Reproduce the reference's _axis_bins window math exactly.
// Returns start, length, step (step already max()'d with 1).
__device__ __forceinline__ void axis_bins(float center, float size, int pooled,
                                          int limit, int& start_o, int& len_o,
                                          int& step_o) {
    // jnp .astype(int32) truncates toward zero; C cast does the same.
    int s = (int)(center - size * 0.5f);
    if (s < 0) s = 0;
    int e = (int)(center + size * 0.5f);
    if (e > limit) e = limit;

    int pad_raw = pooled - (e - s);
    if (pad_raw > 0) {
        int pad    = (pad_raw + 1) >> 1;   // ceil(pad_raw/2), pad_raw>0
        int top    = limit - e;
        int bottom = s;
        int ns, ne;
        if (top < pad)          { ns = s - (2 * pad - top);  ne = e + top; }
        else if (bottom < pad)  { ns = s - bottom;           ne = e + (2 * pad - bottom); }
        else                    { ns = s - pad;              ne = e + pad; }
        s = ns; e = ne;
    }
    int length = e - s;
    int step   = length / pooled;          // length > 0 here -> floor div
    if (step < 1) step = 1;                // max(step, 1)
    start_o = s; len_o = length; step_o = step;
}

__global__ __launch_bounds__(NTHR, 2)
void roi_pool_kernel(const float4* __restrict__ fm,     // [B,H,W,C/4]
                     const float*  __restrict__ rois,   // [B,NR,4] (x,y,w,h)
                     float4*       __restrict__ out)    // [B,NR,PH,PW,C/4]
{
    const int bn = blockIdx.x;          // b*NR + n
    const int b  = bn / NR;

    const float x = rois[bn * 4 + 0];
    const float y = rois[bn * 4 + 1];
    const float w = rois[bn * 4 + 2];
    const float h = rois[bn * 4 + 3];

    int rs, rlen, rstep;  axis_bins(y, h, PH, H, rs, rlen, rstep);
    int cs, clen, cstep;  axis_bins(x, w, PW, W, cs, clen, cstep);

    const int lane = threadIdx.x & (C4 - 1);   // channel-group (0..63)
    const int grp  = threadIdx.x >> 6;         // bin group (0..7)

    const float4* fmb  = fm  + (size_t)b * H * W * C4;
    float4*       outb = out + (size_t)bn * PH * PW * C4;

    #pragma unroll
    for (int bin = grp; bin < PH * PW; bin += NGRP) {
        const int ph = bin / PW;
        const int pw = bin - ph * PW;

        // Row range for this bin (rel in [ph*step, ...)), clamped to [0, H)
        int r0 = rs + ph * rstep;
        int r1 = (ph == PH - 1) ? (rs + rlen) : (r0 + rstep);
        if (r0 < 0) r0 = 0;
        if (r1 > H) r1 = H;

        int c0 = cs + pw * cstep;
        int c1 = (pw == PW - 1) ? (cs + clen) : (c0 + cstep);
        if (c0 < 0) c0 = 0;
        if (c1 > W) c1 = W;

        float4 m;
        m.x = -CUDART_INF_F; m.y = -CUDART_INF_F;
        m.z = -CUDART_INF_F; m.w = -CUDART_INF_F;

        for (int r = r0; r < r1; ++r) {
            const float4* row = fmb + ((size_t)r * W) * C4 + lane;
            // columns are contiguous positions; loads independent -> MLP
            for (int cc = c0; cc < c1; ++cc) {
                float4 v = __ldg(row + (size_t)cc * C4);
                m.x = fmaxf(m.x, v.x);
                m.y = fmaxf(m.y, v.y);
                m.z = fmaxf(m.z, v.z);
                m.w = fmaxf(m.w, v.w);
            }
        }

        outb[(size_t)bin * C4 + lane] = m;
    }
}

extern "C" void kernel_launch(void* const* d_in, const int* in_sizes, int n_in,
                              void* d_out, int out_size) {
    // metadata order: feature_map [B*H*W*C], rois [B*NR*4]
    const float* fm   = (const float*)d_in[0];
    const float* rois = (const float*)d_in[1];
    // Defensive: identify by size in case of ordering surprises.
    if (n_in >= 2 && in_sizes[0] == B * NR * 4 && in_sizes[1] == B * H * W * C) {
        fm   = (const float*)d_in[1];
        rois = (const float*)d_in[0];
    }

    roi_pool_kernel<<<B * NR, NTHR>>>(
        (const float4*)fm, rois, (float4*)d_out);
}

// round 2
// speedup vs baseline: 1.3483x; 1.3483x over previous
#include <cuda_runtime.h>
#include <math_constants.h>

// Problem constants (from reference setup_inputs)
constexpr int B  = 4;
constexpr int H  = 64;
constexpr int W  = 64;
constexpr int C  = 256;
constexpr int NR = 256;   // rois per image
constexpr int PH = 7;
constexpr int PW = 7;

constexpr int C4    = C / 4;       // float4 groups per position = 64
constexpr int NGRP  = 4;           // pw-bin groups per block
constexpr int NTHR  = NGRP * C4;   // 256 threads

// Reproduce the reference's _axis_bins window math exactly.
__device__ __forceinline__ void axis_bins(float center, float size, int pooled,
                                          int limit, int& start_o, int& len_o,
                                          int& step_o) {
    int s = (int)(center - size * 0.5f);   // trunc-toward-zero == astype(int32)
    if (s < 0) s = 0;
    int e = (int)(center + size * 0.5f);
    if (e > limit) e = limit;

    int pad_raw = pooled - (e - s);
    if (pad_raw > 0) {
        int pad    = (pad_raw + 1) >> 1;   // ceil(pad_raw/2), pad_raw>0
        int top    = limit - e;
        int bottom = s;
        int ns, ne;
        if (top < pad)          { ns = s - (2 * pad - top);  ne = e + top; }
        else if (bottom < pad)  { ns = s - bottom;           ne = e + (2 * pad - bottom); }
        else                    { ns = s - pad;              ne = e + pad; }
        s = ns; e = ne;
    }
    int length = e - s;
    int step   = length / pooled;
    if (step < 1) step = 1;
    start_o = s; len_o = length; step_o = step;
}

__global__ __launch_bounds__(NTHR, 6)
void roi_pool_kernel(const float4* __restrict__ fm,     // [B,H,W,C/4]
                     const float*  __restrict__ rois,   // [B,NR,4] (x,y,w,h)
                     float4*       __restrict__ out)    // [B,NR,PH,PW,C/4]
{
    const int bn = blockIdx.x;          // b*NR + n
    const int b  = bn >> 8;             // NR == 256
    const int ph = blockIdx.y;          // row-bin handled by this block

    const float x = rois[bn * 4 + 0];
    const float y = rois[bn * 4 + 1];
    const float w = rois[bn * 4 + 2];
    const float h = rois[bn * 4 + 3];

    int rs, rlen, rstep;  axis_bins(y, h, PH, H, rs, rlen, rstep);
    int cs, clen, cstep;  axis_bins(x, w, PW, W, cs, clen, cstep);

    // Row band for this block's ph bin, clamped to the map.
    int r0 = rs + ph * rstep;
    int r1 = (ph == PH - 1) ? (rs + rlen) : (r0 + rstep);
    if (r0 < 0) r0 = 0;
    if (r1 > H) r1 = H;

    const int lane = threadIdx.x & (C4 - 1);   // channel-group (0..63)
    const int grp  = threadIdx.x >> 6;         // pw-bin group (0..3)

    const float4* fmb  = fm  + (size_t)b * (H * W * C4) + lane;
    float4*       outb = out + ((size_t)bn * PH + ph) * (PW * C4) + lane;

    for (int pw = grp; pw < PW; pw += NGRP) {
        int c0 = cs + pw * cstep;
        int c1 = (pw == PW - 1) ? (cs + clen) : (c0 + cstep);
        if (c0 < 0) c0 = 0;
        if (c1 > W) c1 = W;

        float4 m;
        m.x = -CUDART_INF_F; m.y = -CUDART_INF_F;
        m.z = -CUDART_INF_F; m.w = -CUDART_INF_F;

        // 2x2 clamped-duplicate unroll: 4 independent LDG.128 per iteration.
        // Duplicate (clamped) loads re-hit L1 lines already fetched this
        // iteration, so no extra L2 traffic; code stays branch-free.
        for (int r = r0; r < r1; r += 2) {
            int rb = r + 1 < r1 ? r + 1 : r1 - 1;
            const float4* p0 = fmb + (r  * W) * C4;
            const float4* p1 = fmb + (rb * W) * C4;
            for (int cc = c0; cc < c1; cc += 2) {
                int cb = cc + 1 < c1 ? cc + 1 : c1 - 1;
                float4 v00 = __ldg(p0 + cc * C4);
                float4 v01 = __ldg(p0 + cb * C4);
                float4 v10 = __ldg(p1 + cc * C4);
                float4 v11 = __ldg(p1 + cb * C4);
                float4 a, bb;
                a.x  = fmaxf(v00.x, v01.x);  a.y  = fmaxf(v00.y, v01.y);
                a.z  = fmaxf(v00.z, v01.z);  a.w  = fmaxf(v00.w, v01.w);
                bb.x = fmaxf(v10.x, v11.x);  bb.y = fmaxf(v10.y, v11.y);
                bb.z = fmaxf(v10.z, v11.z);  bb.w = fmaxf(v10.w, v11.w);
                m.x = fmaxf(m.x, fmaxf(a.x, bb.x));
                m.y = fmaxf(m.y, fmaxf(a.y, bb.y));
                m.z = fmaxf(m.z, fmaxf(a.z, bb.z));
                m.w = fmaxf(m.w, fmaxf(a.w, bb.w));
            }
        }

        outb[pw * C4] = m;
    }
}

extern "C" void kernel_launch(void* const* d_in, const int* in_sizes, int n_in,
                              void* d_out, int out_size) {
    const float* fm   = (const float*)d_in[0];
    const float* rois = (const float*)d_in[1];
    if (n_in >= 2 && in_sizes[0] == B * NR * 4 && in_sizes[1] == B * H * W * C) {
        fm   = (const float*)d_in[1];
        rois = (const float*)d_in[0];
    }

    dim3 grid(B * NR, PH);
    roi_pool_kernel<<<grid, NTHR>>>((const float4*)fm, rois, (float4*)d_out);
}